// round 1
// baseline (speedup 1.0000x reference)
#include <cuda_runtime.h>
#include <cuda_bf16.h>
#include <stdint.h>

// Problem constants (fixed by the dataset)
#define MAXN 100000
#define DIN  64
#define DOUT 64

// Scratch (device globals — no allocation allowed)
__device__ float g_h[MAXN * DOUT];      // h = x @ W
__device__ float g_deg[MAXN];           // degree (init 1.0 for self-loop)
__device__ float g_dinv[MAXN];          // rsqrt(deg)

// ---------------------------------------------------------------------------
// K1: h = x @ W  (tiled, W in smem), also init deg[row] = 1.0 (self loop)
// block: (16,16) -> 16 rows per block, 16 threads per row, 4 output cols each
// ---------------------------------------------------------------------------
__global__ void __launch_bounds__(256) gemm_kernel(
    const float* __restrict__ x, const float* __restrict__ W,
    float* __restrict__ h, float* __restrict__ deg, int n)
{
    __shared__ float Ws[DIN * DOUT];   // 16 KB
    __shared__ float xs[16][DIN];      // 4 KB

    const int tx = threadIdx.x;        // 0..15
    const int ty = threadIdx.y;        // 0..15
    const int tid = ty * 16 + tx;

    // load W (4096 floats) as float4
    const float4* W4 = reinterpret_cast<const float4*>(W);
    float4* Ws4 = reinterpret_cast<float4*>(Ws);
    #pragma unroll
    for (int i = tid; i < (DIN * DOUT) / 4; i += 256) Ws4[i] = W4[i];

    const int row = blockIdx.x * 16 + ty;
    if (row < n) {
        // 16 threads load one row of x (64 floats) as float4
        reinterpret_cast<float4*>(xs[ty])[tx] =
            reinterpret_cast<const float4*>(x + (size_t)row * DIN)[tx];
    }
    __syncthreads();

    if (row < n) {
        float4 acc = make_float4(0.f, 0.f, 0.f, 0.f);
        #pragma unroll
        for (int d = 0; d < DIN; d++) {
            const float xv = xs[ty][d];
            const float4 w = *reinterpret_cast<const float4*>(&Ws[d * DOUT + tx * 4]);
            acc.x = fmaf(xv, w.x, acc.x);
            acc.y = fmaf(xv, w.y, acc.y);
            acc.z = fmaf(xv, w.z, acc.z);
            acc.w = fmaf(xv, w.w, acc.w);
        }
        reinterpret_cast<float4*>(h + (size_t)row * DOUT)[tx] = acc;
        if (tx == 0) deg[row] = 1.0f;   // self-loop contribution to degree
    }
}

// ---------------------------------------------------------------------------
// K2: degree accumulation over target (col) index
// ---------------------------------------------------------------------------
__global__ void deg_kernel(const int* __restrict__ col, float* __restrict__ deg, int E)
{
    int i = blockIdx.x * blockDim.x + threadIdx.x;
    if (i < E) atomicAdd(&deg[col[i]], 1.0f);
}

// ---------------------------------------------------------------------------
// K3: dinv = rsqrt(deg)   (deg >= 1 always due to self loops)
// ---------------------------------------------------------------------------
__global__ void dinv_kernel(const float* __restrict__ deg, float* __restrict__ dinv, int n)
{
    int i = blockIdx.x * blockDim.x + threadIdx.x;
    if (i < n) dinv[i] = rsqrtf(deg[i]);
}

// ---------------------------------------------------------------------------
// K4: edge scatter.  One 16-lane group per edge; each lane moves a float4.
//     out[col] += dinv[row]*dinv[col] * h[row]
// ---------------------------------------------------------------------------
__global__ void __launch_bounds__(256) scatter_kernel(
    const int* __restrict__ rowArr, const int* __restrict__ colArr,
    const float* __restrict__ dinv, const float* __restrict__ h,
    float* __restrict__ out, int E)
{
    const int gid  = blockIdx.x * blockDim.x + threadIdx.x;
    const int e    = gid >> 4;
    const int lane = gid & 15;
    if (e >= E) return;

    const int r = __ldg(&rowArr[e]);
    const int c = __ldg(&colArr[e]);
    const float norm = __ldg(&dinv[r]) * __ldg(&dinv[c]);

    const float4 hv = reinterpret_cast<const float4*>(h + (size_t)r * DOUT)[lane];
    const float vx = norm * hv.x;
    const float vy = norm * hv.y;
    const float vz = norm * hv.z;
    const float vw = norm * hv.w;

    float* dst = out + (size_t)c * DOUT + lane * 4;
    asm volatile("red.global.add.v4.f32 [%0], {%1, %2, %3, %4};"
                 :: "l"(dst), "f"(vx), "f"(vy), "f"(vz), "f"(vw)
                 : "memory");
}

// ---------------------------------------------------------------------------
// K5: epilogue: out = relu(out + dinv[i]^2 * h[i] + b)
//     one thread per float4 (n*16 units)
// ---------------------------------------------------------------------------
__global__ void __launch_bounds__(256) epilogue_kernel(
    const float* __restrict__ h, const float* __restrict__ dinv,
    const float* __restrict__ b, float* __restrict__ out, int n)
{
    const int i = blockIdx.x * blockDim.x + threadIdx.x;    // float4 index
    if (i >= n * (DOUT / 4)) return;
    const int node = i >> 4;
    const int q    = i & 15;

    float s = dinv[node];
    s = s * s;

    const float4 hv = reinterpret_cast<const float4*>(h)[i];
    float4 o        = reinterpret_cast<float4*>(out)[i];
    const float4 bb = reinterpret_cast<const float4*>(b)[q];

    o.x = fmaxf(fmaf(s, hv.x, o.x) + bb.x, 0.f);
    o.y = fmaxf(fmaf(s, hv.y, o.y) + bb.y, 0.f);
    o.z = fmaxf(fmaf(s, hv.z, o.z) + bb.z, 0.f);
    o.w = fmaxf(fmaf(s, hv.w, o.w) + bb.w, 0.f);

    reinterpret_cast<float4*>(out)[i] = o;
}

// ---------------------------------------------------------------------------
// kernel_launch
// inputs (metadata order): x [N*64] f32, edge_index [2*E] i32, W [64*64] f32, b [64] f32
// output: [N*64] f32
// ---------------------------------------------------------------------------
extern "C" void kernel_launch(void* const* d_in, const int* in_sizes, int n_in,
                              void* d_out, int out_size)
{
    const float* x  = (const float*)d_in[0];
    const int*   ei = (const int*)  d_in[1];
    const float* W  = (const float*)d_in[2];
    const float* b  = (const float*)d_in[3];
    float* out      = (float*)d_out;

    const int n = in_sizes[0] / DIN;       // 100000
    const int E = in_sizes[1] / 2;         // 1000000
    const int* rowArr = ei;                // source
    const int* colArr = ei + E;            // target

    float* h;    cudaGetSymbolAddress((void**)&h,    g_h);
    float* deg;  cudaGetSymbolAddress((void**)&deg,  g_deg);
    float* dinv; cudaGetSymbolAddress((void**)&dinv, g_dinv);

    // zero the output accumulator (graph-capturable async memset)
    cudaMemsetAsync(d_out, 0, (size_t)out_size * sizeof(float));

    // K1: GEMM + deg init
    gemm_kernel<<<(n + 15) / 16, dim3(16, 16)>>>(x, W, h, deg, n);

    // K2: degree over targets
    deg_kernel<<<(E + 255) / 256, 256>>>(colArr, deg, E);

    // K3: dinv
    dinv_kernel<<<(n + 255) / 256, 256>>>(deg, dinv, n);

    // K4: scatter (16 lanes per edge)
    {
        const long long threads = (long long)E * 16;
        scatter_kernel<<<(int)((threads + 255) / 256), 256>>>(rowArr, colArr, dinv, h, out, E);
    }

    // K5: epilogue
    {
        const int units = n * (DOUT / 4);
        epilogue_kernel<<<(units + 255) / 256, 256>>>(h, dinv, b, out, n);
    }
}

// round 2
// speedup vs baseline: 1.2901x; 1.2901x over previous
#include <cuda_runtime.h>
#include <cuda_bf16.h>
#include <stdint.h>

#define MAXN 100000
#define DIN  64
#define DOUT 64

// Scratch (device globals — no allocation allowed)
__device__ float g_h[MAXN * DOUT];      // h' = dinv[row] * (x @ W)
__device__ float g_deg[MAXN];           // edge count per target (0-init, self-loop added later)
__device__ float g_dinv[MAXN];          // rsqrt(deg + 1)

// ---------------------------------------------------------------------------
// K1: degree accumulation over target (col) index
// ---------------------------------------------------------------------------
__global__ void deg_kernel(const int* __restrict__ col, float* __restrict__ deg, int E)
{
    int i = blockIdx.x * blockDim.x + threadIdx.x;
    if (i < E) atomicAdd(&deg[col[i]], 1.0f);
}

// ---------------------------------------------------------------------------
// K2: dinv = rsqrt(deg + 1)   (+1 = self loop)
// ---------------------------------------------------------------------------
__global__ void dinv_kernel(const float* __restrict__ deg, float* __restrict__ dinv, int n)
{
    int i = blockIdx.x * blockDim.x + threadIdx.x;
    if (i < n) dinv[i] = rsqrtf(deg[i] + 1.0f);
}

// ---------------------------------------------------------------------------
// K3: h' = dinv[row] * (x @ W)
// Register-tiled: block(16,16)=256 thr, each thread 4 rows x 4 cols.
// Block covers 64 rows. x stored transposed in smem -> per d-step each thread
// does 1 LDS.128 (4 x-vals) + 1 LDS.128 (4 W-vals) for 16 FMAs.
// ---------------------------------------------------------------------------
__global__ void __launch_bounds__(256) gemm_kernel(
    const float* __restrict__ x, const float* __restrict__ W,
    const float* __restrict__ dinv, float* __restrict__ h, int n)
{
    __shared__ float Ws[DIN * DOUT];      // 16 KB, Ws[d*64+c]
    __shared__ float xst[DIN][64];        // 16 KB, xst[d][local_row]

    const int tx  = threadIdx.x;          // 0..15 : col-quad
    const int ty  = threadIdx.y;          // 0..15 : row-quad
    const int tid = ty * 16 + tx;
    const int row0 = blockIdx.x * 64;

    // load W as float4
    {
        const float4* W4 = reinterpret_cast<const float4*>(W);
        float4* Ws4 = reinterpret_cast<float4*>(Ws);
        #pragma unroll
        for (int i = tid; i < (DIN * DOUT) / 4; i += 256) Ws4[i] = W4[i];
    }

    // load x transposed: thread t handles local row (t&63), d-chunks based on t>>6
    {
        const int lr = tid & 63;                  // local row
        const int g  = tid >> 6;                  // 0..3
        const int grow = row0 + lr;
        if (grow < n) {
            #pragma unroll
            for (int k = 0; k < 4; k++) {
                const int d0 = g * 16 + k * 4;
                const float4 v = reinterpret_cast<const float4*>(x + (size_t)grow * DIN)[d0 >> 2];
                xst[d0 + 0][lr] = v.x;
                xst[d0 + 1][lr] = v.y;
                xst[d0 + 2][lr] = v.z;
                xst[d0 + 3][lr] = v.w;
            }
        }
    }
    __syncthreads();

    float4 acc0 = make_float4(0,0,0,0);
    float4 acc1 = make_float4(0,0,0,0);
    float4 acc2 = make_float4(0,0,0,0);
    float4 acc3 = make_float4(0,0,0,0);

    #pragma unroll
    for (int d = 0; d < DIN; d++) {
        const float4 xv = *reinterpret_cast<const float4*>(&xst[d][ty * 4]);
        const float4 wv = *reinterpret_cast<const float4*>(&Ws[d * DOUT + tx * 4]);
        acc0.x = fmaf(xv.x, wv.x, acc0.x); acc0.y = fmaf(xv.x, wv.y, acc0.y);
        acc0.z = fmaf(xv.x, wv.z, acc0.z); acc0.w = fmaf(xv.x, wv.w, acc0.w);
        acc1.x = fmaf(xv.y, wv.x, acc1.x); acc1.y = fmaf(xv.y, wv.y, acc1.y);
        acc1.z = fmaf(xv.y, wv.z, acc1.z); acc1.w = fmaf(xv.y, wv.w, acc1.w);
        acc2.x = fmaf(xv.z, wv.x, acc2.x); acc2.y = fmaf(xv.z, wv.y, acc2.y);
        acc2.z = fmaf(xv.z, wv.z, acc2.z); acc2.w = fmaf(xv.z, wv.w, acc2.w);
        acc3.x = fmaf(xv.w, wv.x, acc3.x); acc3.y = fmaf(xv.w, wv.y, acc3.y);
        acc3.z = fmaf(xv.w, wv.z, acc3.z); acc3.w = fmaf(xv.w, wv.w, acc3.w);
    }

    // scaled store: h'[r] = dinv[r] * acc
    const int lr0 = ty * 4;
    float4 accs[4] = {acc0, acc1, acc2, acc3};
    #pragma unroll
    for (int i = 0; i < 4; i++) {
        const int grow = row0 + lr0 + i;
        if (grow < n) {
            const float s = __ldg(&dinv[grow]);
            float4 a = accs[i];
            a.x *= s; a.y *= s; a.z *= s; a.w *= s;
            reinterpret_cast<float4*>(h + (size_t)grow * DOUT)[tx] = a;
        }
    }
}

// ---------------------------------------------------------------------------
// K4: edge scatter: out[col] += h'[row].  16 lanes per edge, float4 each.
// Pure copy: LDG idx -> LDG.128 -> RED.128, no arithmetic.
// ---------------------------------------------------------------------------
__global__ void __launch_bounds__(256) scatter_kernel(
    const int* __restrict__ rowArr, const int* __restrict__ colArr,
    const float* __restrict__ h, float* __restrict__ out, int E)
{
    const int gid  = blockIdx.x * blockDim.x + threadIdx.x;
    const int e    = gid >> 4;
    const int lane = gid & 15;
    if (e >= E) return;

    const int r = __ldg(&rowArr[e]);
    const int c = __ldg(&colArr[e]);

    const float4 hv = reinterpret_cast<const float4*>(h + (size_t)r * DOUT)[lane];
    float* dst = out + (size_t)c * DOUT + lane * 4;
    asm volatile("red.global.add.v4.f32 [%0], {%1, %2, %3, %4};"
                 :: "l"(dst), "f"(hv.x), "f"(hv.y), "f"(hv.z), "f"(hv.w)
                 : "memory");
}

// ---------------------------------------------------------------------------
// K5: epilogue: out = relu(dinv[i] * (out[i] + h'[i]) + b)
// ---------------------------------------------------------------------------
__global__ void __launch_bounds__(256) epilogue_kernel(
    const float* __restrict__ h, const float* __restrict__ dinv,
    const float* __restrict__ b, float* __restrict__ out, int n)
{
    const int i = blockIdx.x * blockDim.x + threadIdx.x;    // float4 index
    if (i >= n * (DOUT / 4)) return;
    const int node = i >> 4;
    const int q    = i & 15;

    const float s = dinv[node];
    const float4 hv = reinterpret_cast<const float4*>(h)[i];
    float4 o        = reinterpret_cast<float4*>(out)[i];
    const float4 bb = reinterpret_cast<const float4*>(b)[q];

    o.x = fmaxf(fmaf(s, o.x + hv.x, bb.x), 0.f);
    o.y = fmaxf(fmaf(s, o.y + hv.y, bb.y), 0.f);
    o.z = fmaxf(fmaf(s, o.z + hv.z, bb.z), 0.f);
    o.w = fmaxf(fmaf(s, o.w + hv.w, bb.w), 0.f);

    reinterpret_cast<float4*>(out)[i] = o;
}

// ---------------------------------------------------------------------------
// kernel_launch
// inputs: x [N*64] f32, edge_index [2*E] i32, W [64*64] f32, b [64] f32
// output: [N*64] f32
// ---------------------------------------------------------------------------
extern "C" void kernel_launch(void* const* d_in, const int* in_sizes, int n_in,
                              void* d_out, int out_size)
{
    const float* x  = (const float*)d_in[0];
    const int*   ei = (const int*)  d_in[1];
    const float* W  = (const float*)d_in[2];
    const float* b  = (const float*)d_in[3];
    float* out      = (float*)d_out;

    const int n = in_sizes[0] / DIN;       // 100000
    const int E = in_sizes[1] / 2;         // 1000000
    const int* rowArr = ei;                // source
    const int* colArr = ei + E;            // target

    float* h;    cudaGetSymbolAddress((void**)&h,    g_h);
    float* deg;  cudaGetSymbolAddress((void**)&deg,  g_deg);
    float* dinv; cudaGetSymbolAddress((void**)&dinv, g_dinv);

    // zero accumulators (graph-capturable async memsets)
    cudaMemsetAsync(d_out, 0, (size_t)out_size * sizeof(float));
    cudaMemsetAsync(deg, 0, (size_t)n * sizeof(float));

    // K1: degree over targets
    deg_kernel<<<(E + 255) / 256, 256>>>(colArr, deg, E);

    // K2: dinv
    dinv_kernel<<<(n + 255) / 256, 256>>>(deg, dinv, n);

    // K3: GEMM with dinv-scaled store
    gemm_kernel<<<(n + 63) / 64, dim3(16, 16)>>>(x, W, dinv, h, n);

    // K4: scatter (16 lanes per edge, pure vector red)
    {
        const long long threads = (long long)E * 16;
        scatter_kernel<<<(int)((threads + 255) / 256), 256>>>(rowArr, colArr, h, out, E);
    }

    // K5: epilogue
    {
        const int units = n * (DOUT / 4);
        epilogue_kernel<<<(units + 255) / 256, 256>>>(h, dinv, b, out, n);
    }
}

// round 3
// speedup vs baseline: 1.6279x; 1.2618x over previous
#include <cuda_runtime.h>
#include <cuda_bf16.h>
#include <stdint.h>

#define MAXN 100000
#define MAXE 1000000
#define DIN  64
#define DOUT 64
#define SCAN_B 1024

// Scratch (device globals — no allocation allowed)
__device__ float g_h[MAXN * DOUT];       // h' = dinv[row] * (x @ W)
__device__ int   g_cnt[MAXN];            // in-degree counts
__device__ int   g_rowptr[MAXN + 1];     // CSR row pointers (by target)
__device__ int   g_cursor[MAXN];         // fill cursors
__device__ int   g_csrsrc[MAXE];         // CSR source indices
__device__ int   g_blksum[256];          // scan partials
__device__ float g_dinv[MAXN];           // rsqrt(deg + 1)

// ---------------------------------------------------------------------------
// K1: in-degree count over target (col) index
// ---------------------------------------------------------------------------
__global__ void count_kernel(const int* __restrict__ col, int* __restrict__ cnt, int E)
{
    int i = blockIdx.x * blockDim.x + threadIdx.x;
    if (i < E) atomicAdd(&cnt[col[i]], 1);
}

// ---------------------------------------------------------------------------
// K2: dinv = rsqrt(cnt + 1)
// ---------------------------------------------------------------------------
__global__ void dinv_kernel(const int* __restrict__ cnt, float* __restrict__ dinv, int n)
{
    int i = blockIdx.x * blockDim.x + threadIdx.x;
    if (i < n) dinv[i] = rsqrtf((float)cnt[i] + 1.0f);
}

// ---------------------------------------------------------------------------
// K3a/b/c: exclusive scan of cnt -> rowptr  (3-phase)
// ---------------------------------------------------------------------------
__global__ void scan_block_kernel(const int* __restrict__ cnt, int* __restrict__ rowptr,
                                  int* __restrict__ blksum, int n)
{
    __shared__ int sh[SCAN_B];
    const int t = threadIdx.x;
    const int i = blockIdx.x * SCAN_B + t;
    const int v = (i < n) ? cnt[i] : 0;
    sh[t] = v;
    __syncthreads();
    #pragma unroll
    for (int off = 1; off < SCAN_B; off <<= 1) {
        int add = (t >= off) ? sh[t - off] : 0;
        __syncthreads();
        sh[t] += add;
        __syncthreads();
    }
    if (i < n) rowptr[i] = sh[t] - v;           // exclusive
    if (t == SCAN_B - 1) blksum[blockIdx.x] = sh[t];
}

__global__ void scan_sums_kernel(int* __restrict__ blksum, int nb)
{
    __shared__ int sh[256];
    const int t = threadIdx.x;
    const int v = (t < nb) ? blksum[t] : 0;
    sh[t] = v;
    __syncthreads();
    #pragma unroll
    for (int off = 1; off < 256; off <<= 1) {
        int add = (t >= off) ? sh[t - off] : 0;
        __syncthreads();
        sh[t] += add;
        __syncthreads();
    }
    if (t < nb) blksum[t] = sh[t] - v;          // exclusive
}

__global__ void scan_add_kernel(int* __restrict__ rowptr, const int* __restrict__ blksum,
                                int n, int E)
{
    const int i = blockIdx.x * SCAN_B + threadIdx.x;
    if (i < n) rowptr[i] += blksum[blockIdx.x];
    if (i == 0) rowptr[n] = E;
}

// ---------------------------------------------------------------------------
// K4: CSR fill: csr_src[rowptr[col] + cursor[col]++] = row
// ---------------------------------------------------------------------------
__global__ void fill_kernel(const int* __restrict__ rowArr, const int* __restrict__ colArr,
                            const int* __restrict__ rowptr, int* __restrict__ cursor,
                            int* __restrict__ csrsrc, int E)
{
    int i = blockIdx.x * blockDim.x + threadIdx.x;
    if (i < E) {
        const int c = colArr[i];
        const int pos = atomicAdd(&cursor[c], 1);
        csrsrc[rowptr[c] + pos] = rowArr[i];
    }
}

// ---------------------------------------------------------------------------
// K5: h' = dinv[row] * (x @ W)   (register-tiled 4x4, unchanged from R2)
// ---------------------------------------------------------------------------
__global__ void __launch_bounds__(256) gemm_kernel(
    const float* __restrict__ x, const float* __restrict__ W,
    const float* __restrict__ dinv, float* __restrict__ h, int n)
{
    __shared__ float Ws[DIN * DOUT];
    __shared__ float xst[DIN][64];

    const int tx  = threadIdx.x;
    const int ty  = threadIdx.y;
    const int tid = ty * 16 + tx;
    const int row0 = blockIdx.x * 64;

    {
        const float4* W4 = reinterpret_cast<const float4*>(W);
        float4* Ws4 = reinterpret_cast<float4*>(Ws);
        #pragma unroll
        for (int i = tid; i < (DIN * DOUT) / 4; i += 256) Ws4[i] = W4[i];
    }
    {
        const int lr = tid & 63;
        const int g  = tid >> 6;
        const int grow = row0 + lr;
        if (grow < n) {
            #pragma unroll
            for (int k = 0; k < 4; k++) {
                const int d0 = g * 16 + k * 4;
                const float4 v = reinterpret_cast<const float4*>(x + (size_t)grow * DIN)[d0 >> 2];
                xst[d0 + 0][lr] = v.x;
                xst[d0 + 1][lr] = v.y;
                xst[d0 + 2][lr] = v.z;
                xst[d0 + 3][lr] = v.w;
            }
        }
    }
    __syncthreads();

    float4 acc0 = make_float4(0,0,0,0), acc1 = make_float4(0,0,0,0);
    float4 acc2 = make_float4(0,0,0,0), acc3 = make_float4(0,0,0,0);

    #pragma unroll
    for (int d = 0; d < DIN; d++) {
        const float4 xv = *reinterpret_cast<const float4*>(&xst[d][ty * 4]);
        const float4 wv = *reinterpret_cast<const float4*>(&Ws[d * DOUT + tx * 4]);
        acc0.x = fmaf(xv.x, wv.x, acc0.x); acc0.y = fmaf(xv.x, wv.y, acc0.y);
        acc0.z = fmaf(xv.x, wv.z, acc0.z); acc0.w = fmaf(xv.x, wv.w, acc0.w);
        acc1.x = fmaf(xv.y, wv.x, acc1.x); acc1.y = fmaf(xv.y, wv.y, acc1.y);
        acc1.z = fmaf(xv.y, wv.z, acc1.z); acc1.w = fmaf(xv.y, wv.w, acc1.w);
        acc2.x = fmaf(xv.z, wv.x, acc2.x); acc2.y = fmaf(xv.z, wv.y, acc2.y);
        acc2.z = fmaf(xv.z, wv.z, acc2.z); acc2.w = fmaf(xv.z, wv.w, acc2.w);
        acc3.x = fmaf(xv.w, wv.x, acc3.x); acc3.y = fmaf(xv.w, wv.y, acc3.y);
        acc3.z = fmaf(xv.w, wv.z, acc3.z); acc3.w = fmaf(xv.w, wv.w, acc3.w);
    }

    const int lr0 = ty * 4;
    float4 accs[4] = {acc0, acc1, acc2, acc3};
    #pragma unroll
    for (int i = 0; i < 4; i++) {
        const int grow = row0 + lr0 + i;
        if (grow < n) {
            const float s = __ldg(&dinv[grow]);
            float4 a = accs[i];
            a.x *= s; a.y *= s; a.z *= s; a.w *= s;
            reinterpret_cast<float4*>(h + (size_t)grow * DOUT)[tx] = a;
        }
    }
}

// ---------------------------------------------------------------------------
// K6: aggregate + epilogue. 16 lanes per target node, float4 per lane.
//     out[i] = relu(dinv[i] * (h'[i] + sum_{j in CSR[i]} h'[j]) + b)
// ---------------------------------------------------------------------------
__global__ void __launch_bounds__(256) aggregate_kernel(
    const int* __restrict__ rowptr, const int* __restrict__ csrsrc,
    const float* __restrict__ h, const float* __restrict__ dinv,
    const float* __restrict__ b, float* __restrict__ out, int n)
{
    const int gid  = blockIdx.x * blockDim.x + threadIdx.x;
    const int node = gid >> 4;
    const int lane = gid & 15;
    if (node >= n) return;

    const int beg = __ldg(&rowptr[node]);
    const int end = __ldg(&rowptr[node + 1]);

    // self loop (h' already dinv-scaled)
    float4 acc = reinterpret_cast<const float4*>(h + (size_t)node * DOUT)[lane];

    int k = beg;
    for (; k + 3 < end; k += 4) {
        const int s0 = __ldg(&csrsrc[k + 0]);
        const int s1 = __ldg(&csrsrc[k + 1]);
        const int s2 = __ldg(&csrsrc[k + 2]);
        const int s3 = __ldg(&csrsrc[k + 3]);
        const float4 v0 = reinterpret_cast<const float4*>(h + (size_t)s0 * DOUT)[lane];
        const float4 v1 = reinterpret_cast<const float4*>(h + (size_t)s1 * DOUT)[lane];
        const float4 v2 = reinterpret_cast<const float4*>(h + (size_t)s2 * DOUT)[lane];
        const float4 v3 = reinterpret_cast<const float4*>(h + (size_t)s3 * DOUT)[lane];
        acc.x += (v0.x + v1.x) + (v2.x + v3.x);
        acc.y += (v0.y + v1.y) + (v2.y + v3.y);
        acc.z += (v0.z + v1.z) + (v2.z + v3.z);
        acc.w += (v0.w + v1.w) + (v2.w + v3.w);
    }
    for (; k < end; k++) {
        const int s = __ldg(&csrsrc[k]);
        const float4 v = reinterpret_cast<const float4*>(h + (size_t)s * DOUT)[lane];
        acc.x += v.x; acc.y += v.y; acc.z += v.z; acc.w += v.w;
    }

    const float sc = __ldg(&dinv[node]);
    const float4 bb = reinterpret_cast<const float4*>(b)[lane];
    float4 o;
    o.x = fmaxf(fmaf(sc, acc.x, bb.x), 0.f);
    o.y = fmaxf(fmaf(sc, acc.y, bb.y), 0.f);
    o.z = fmaxf(fmaf(sc, acc.z, bb.z), 0.f);
    o.w = fmaxf(fmaf(sc, acc.w, bb.w), 0.f);
    reinterpret_cast<float4*>(out + (size_t)node * DOUT)[lane] = o;
}

// ---------------------------------------------------------------------------
// kernel_launch
// inputs: x [N*64] f32, edge_index [2*E] i32, W [64*64] f32, b [64] f32
// ---------------------------------------------------------------------------
extern "C" void kernel_launch(void* const* d_in, const int* in_sizes, int n_in,
                              void* d_out, int out_size)
{
    const float* x  = (const float*)d_in[0];
    const int*   ei = (const int*)  d_in[1];
    const float* W  = (const float*)d_in[2];
    const float* b  = (const float*)d_in[3];
    float* out      = (float*)d_out;

    const int n = in_sizes[0] / DIN;       // 100000
    const int E = in_sizes[1] / 2;         // 1000000
    const int* rowArr = ei;
    const int* colArr = ei + E;

    float* h;     cudaGetSymbolAddress((void**)&h,     g_h);
    int* cnt;     cudaGetSymbolAddress((void**)&cnt,   g_cnt);
    int* rowptr;  cudaGetSymbolAddress((void**)&rowptr,g_rowptr);
    int* cursor;  cudaGetSymbolAddress((void**)&cursor,g_cursor);
    int* csrsrc;  cudaGetSymbolAddress((void**)&csrsrc,g_csrsrc);
    int* blksum;  cudaGetSymbolAddress((void**)&blksum,g_blksum);
    float* dinv;  cudaGetSymbolAddress((void**)&dinv,  g_dinv);

    cudaMemsetAsync(cnt,    0, (size_t)n * sizeof(int));
    cudaMemsetAsync(cursor, 0, (size_t)n * sizeof(int));

    // K1: counts
    count_kernel<<<(E + 255) / 256, 256>>>(colArr, cnt, E);

    // K2: dinv
    dinv_kernel<<<(n + 255) / 256, 256>>>(cnt, dinv, n);

    // K3: scan cnt -> rowptr
    const int nb = (n + SCAN_B - 1) / SCAN_B;
    scan_block_kernel<<<nb, SCAN_B>>>(cnt, rowptr, blksum, n);
    scan_sums_kernel<<<1, 256>>>(blksum, nb);
    scan_add_kernel<<<nb, SCAN_B>>>(rowptr, blksum, n, E);

    // K4: CSR fill
    fill_kernel<<<(E + 255) / 256, 256>>>(rowArr, colArr, rowptr, cursor, csrsrc, E);

    // K5: GEMM (h' = dinv * xW)
    gemm_kernel<<<(n + 63) / 64, dim3(16, 16)>>>(x, W, dinv, h, n);

    // K6: aggregate + epilogue
    {
        const long long threads = (long long)n * 16;
        aggregate_kernel<<<(int)((threads + 255) / 256), 256>>>(
            rowptr, csrsrc, h, dinv, b, out, n);
    }
}

// round 4
// speedup vs baseline: 1.8013x; 1.1065x over previous
#include <cuda_runtime.h>
#include <cuda_bf16.h>
#include <stdint.h>

#define MAXN 100000
#define MAXE 1000000
#define DIN  64
#define DOUT 64
#define SCAN_B 1024

// Scratch (device globals — no allocation allowed)
__device__ float g_h[MAXN * DOUT];       // h' = dinv[row] * (x @ W)
__device__ int   g_cnt[MAXN];            // in-degree counts
__device__ int   g_rowptr[MAXN + 1];     // CSR row pointers (by target)
__device__ int   g_cursor[MAXN];         // fill cursors (init = rowptr)
__device__ int   g_csrsrc[MAXE];         // CSR source indices
__device__ int   g_blksum[128];          // scan partials (nb <= 98)
__device__ float g_dinv[MAXN];           // rsqrt(deg + 1)

// ---------------------------------------------------------------------------
// K1: in-degree count over target (col) index
// ---------------------------------------------------------------------------
__global__ void count_kernel(const int* __restrict__ col, int* __restrict__ cnt, int E)
{
    int i = blockIdx.x * blockDim.x + threadIdx.x;
    if (i < E) atomicAdd(&cnt[col[i]], 1);
}

// ---------------------------------------------------------------------------
// K2: scanA — per-block exclusive scan of cnt, block totals, and dinv.
// ---------------------------------------------------------------------------
__global__ void __launch_bounds__(SCAN_B) scanA_kernel(
    const int* __restrict__ cnt, int* __restrict__ rowptr,
    int* __restrict__ blksum, float* __restrict__ dinv, int n)
{
    __shared__ int sh[SCAN_B];
    const int t = threadIdx.x;
    const int i = blockIdx.x * SCAN_B + t;
    const int v = (i < n) ? cnt[i] : 0;
    if (i < n) dinv[i] = rsqrtf((float)v + 1.0f);
    sh[t] = v;
    __syncthreads();
    #pragma unroll
    for (int off = 1; off < SCAN_B; off <<= 1) {
        int add = (t >= off) ? sh[t - off] : 0;
        __syncthreads();
        sh[t] += add;
        __syncthreads();
    }
    if (i < n) rowptr[i] = sh[t] - v;           // exclusive (within block)
    if (t == SCAN_B - 1) blksum[blockIdx.x] = sh[t];
}

// ---------------------------------------------------------------------------
// K3: scanB — each block reduces its prefix of blksum locally, finalizes
//     rowptr, and initializes cursor = rowptr. Block 0 writes rowptr[n]=E.
// ---------------------------------------------------------------------------
__global__ void __launch_bounds__(SCAN_B) scanB_kernel(
    int* __restrict__ rowptr, int* __restrict__ cursor,
    const int* __restrict__ blksum, int n, int E)
{
    __shared__ int red[128];
    const int t = threadIdx.x;
    if (t < 128) {
        int s = 0;
        for (int j = t; j < blockIdx.x; j += 128) s += blksum[j];
        red[t] = s;
    }
    __syncthreads();
    #pragma unroll
    for (int off = 64; off >= 1; off >>= 1) {
        if (t < off) red[t] += red[t + off];
        __syncthreads();
    }
    const int p = red[0];

    const int i = blockIdx.x * SCAN_B + t;
    if (i < n) {
        const int r = rowptr[i] + p;
        rowptr[i] = r;
        cursor[i] = r;
    }
    if (blockIdx.x == 0 && t == 0) rowptr[n] = E;
}

// ---------------------------------------------------------------------------
// K4: fused GEMM (h' = dinv * xW) || CSR fill — block specialization.
// Blocks [0, nGemm): register-tiled GEMM, 64 rows/block.
// Blocks [nGemm, ...): fill 256 edges each.
// ---------------------------------------------------------------------------
__global__ void __launch_bounds__(256) fused_gemm_fill_kernel(
    const float* __restrict__ x, const float* __restrict__ W,
    const float* __restrict__ dinv, float* __restrict__ h,
    const int* __restrict__ rowArr, const int* __restrict__ colArr,
    int* __restrict__ cursor, int* __restrict__ csrsrc,
    int n, int E, int nGemm)
{
    __shared__ float Ws[DIN * DOUT];      // 16 KB
    __shared__ float xst[DIN][64];        // 16 KB

    const int tid = threadIdx.x;

    if (blockIdx.x >= nGemm) {
        // ---- fill branch ----
        const int i = (blockIdx.x - nGemm) * 256 + tid;
        if (i < E) {
            const int c = colArr[i];
            const int slot = atomicAdd(&cursor[c], 1);
            csrsrc[slot] = rowArr[i];
        }
        return;
    }

    // ---- GEMM branch ----
    const int tx = tid & 15;              // col-quad
    const int ty = tid >> 4;              // row-quad
    const int row0 = blockIdx.x * 64;

    {
        const float4* W4 = reinterpret_cast<const float4*>(W);
        float4* Ws4 = reinterpret_cast<float4*>(Ws);
        #pragma unroll
        for (int i = tid; i < (DIN * DOUT) / 4; i += 256) Ws4[i] = W4[i];
    }
    {
        const int lr = tid & 63;
        const int g  = tid >> 6;
        const int grow = row0 + lr;
        if (grow < n) {
            #pragma unroll
            for (int k = 0; k < 4; k++) {
                const int d0 = g * 16 + k * 4;
                const float4 v = reinterpret_cast<const float4*>(x + (size_t)grow * DIN)[d0 >> 2];
                xst[d0 + 0][lr] = v.x;
                xst[d0 + 1][lr] = v.y;
                xst[d0 + 2][lr] = v.z;
                xst[d0 + 3][lr] = v.w;
            }
        }
    }
    __syncthreads();

    float4 acc0 = make_float4(0,0,0,0), acc1 = make_float4(0,0,0,0);
    float4 acc2 = make_float4(0,0,0,0), acc3 = make_float4(0,0,0,0);

    #pragma unroll
    for (int d = 0; d < DIN; d++) {
        const float4 xv = *reinterpret_cast<const float4*>(&xst[d][ty * 4]);
        const float4 wv = *reinterpret_cast<const float4*>(&Ws[d * DOUT + tx * 4]);
        acc0.x = fmaf(xv.x, wv.x, acc0.x); acc0.y = fmaf(xv.x, wv.y, acc0.y);
        acc0.z = fmaf(xv.x, wv.z, acc0.z); acc0.w = fmaf(xv.x, wv.w, acc0.w);
        acc1.x = fmaf(xv.y, wv.x, acc1.x); acc1.y = fmaf(xv.y, wv.y, acc1.y);
        acc1.z = fmaf(xv.y, wv.z, acc1.z); acc1.w = fmaf(xv.y, wv.w, acc1.w);
        acc2.x = fmaf(xv.z, wv.x, acc2.x); acc2.y = fmaf(xv.z, wv.y, acc2.y);
        acc2.z = fmaf(xv.z, wv.z, acc2.z); acc2.w = fmaf(xv.z, wv.w, acc2.w);
        acc3.x = fmaf(xv.w, wv.x, acc3.x); acc3.y = fmaf(xv.w, wv.y, acc3.y);
        acc3.z = fmaf(xv.w, wv.z, acc3.z); acc3.w = fmaf(xv.w, wv.w, acc3.w);
    }

    const int lr0 = ty * 4;
    float4 accs[4] = {acc0, acc1, acc2, acc3};
    #pragma unroll
    for (int i = 0; i < 4; i++) {
        const int grow = row0 + lr0 + i;
        if (grow < n) {
            const float s = __ldg(&dinv[grow]);
            float4 a = accs[i];
            a.x *= s; a.y *= s; a.z *= s; a.w *= s;
            reinterpret_cast<float4*>(h + (size_t)grow * DOUT)[tx] = a;
        }
    }
}

// ---------------------------------------------------------------------------
// K5: aggregate + epilogue. 16 lanes per target node, float4 per lane.
//     out[i] = relu(dinv[i] * (h'[i] + sum_{j in CSR[i]} h'[j]) + b)
// ---------------------------------------------------------------------------
__global__ void __launch_bounds__(256) aggregate_kernel(
    const int* __restrict__ rowptr, const int* __restrict__ csrsrc,
    const float* __restrict__ h, const float* __restrict__ dinv,
    const float* __restrict__ b, float* __restrict__ out, int n)
{
    const int gid  = blockIdx.x * blockDim.x + threadIdx.x;
    const int node = gid >> 4;
    const int lane = gid & 15;
    if (node >= n) return;

    const int beg = __ldg(&rowptr[node]);
    const int end = __ldg(&rowptr[node + 1]);

    // self loop (h' already dinv-scaled)
    float4 acc = reinterpret_cast<const float4*>(h + (size_t)node * DOUT)[lane];

    int k = beg;
    for (; k + 3 < end; k += 4) {
        const int s0 = __ldg(&csrsrc[k + 0]);
        const int s1 = __ldg(&csrsrc[k + 1]);
        const int s2 = __ldg(&csrsrc[k + 2]);
        const int s3 = __ldg(&csrsrc[k + 3]);
        const float4 v0 = reinterpret_cast<const float4*>(h + (size_t)s0 * DOUT)[lane];
        const float4 v1 = reinterpret_cast<const float4*>(h + (size_t)s1 * DOUT)[lane];
        const float4 v2 = reinterpret_cast<const float4*>(h + (size_t)s2 * DOUT)[lane];
        const float4 v3 = reinterpret_cast<const float4*>(h + (size_t)s3 * DOUT)[lane];
        acc.x += (v0.x + v1.x) + (v2.x + v3.x);
        acc.y += (v0.y + v1.y) + (v2.y + v3.y);
        acc.z += (v0.z + v1.z) + (v2.z + v3.z);
        acc.w += (v0.w + v1.w) + (v2.w + v3.w);
    }
    for (; k < end; k++) {
        const int s = __ldg(&csrsrc[k]);
        const float4 v = reinterpret_cast<const float4*>(h + (size_t)s * DOUT)[lane];
        acc.x += v.x; acc.y += v.y; acc.z += v.z; acc.w += v.w;
    }

    const float sc = __ldg(&dinv[node]);
    const float4 bb = reinterpret_cast<const float4*>(b)[lane];
    float4 o;
    o.x = fmaxf(fmaf(sc, acc.x, bb.x), 0.f);
    o.y = fmaxf(fmaf(sc, acc.y, bb.y), 0.f);
    o.z = fmaxf(fmaf(sc, acc.z, bb.z), 0.f);
    o.w = fmaxf(fmaf(sc, acc.w, bb.w), 0.f);
    reinterpret_cast<float4*>(out + (size_t)node * DOUT)[lane] = o;
}

// ---------------------------------------------------------------------------
// kernel_launch
// inputs: x [N*64] f32, edge_index [2*E] i32, W [64*64] f32, b [64] f32
// ---------------------------------------------------------------------------
extern "C" void kernel_launch(void* const* d_in, const int* in_sizes, int n_in,
                              void* d_out, int out_size)
{
    const float* x  = (const float*)d_in[0];
    const int*   ei = (const int*)  d_in[1];
    const float* W  = (const float*)d_in[2];
    const float* b  = (const float*)d_in[3];
    float* out      = (float*)d_out;

    const int n = in_sizes[0] / DIN;       // 100000
    const int E = in_sizes[1] / 2;         // 1000000
    const int* rowArr = ei;
    const int* colArr = ei + E;

    float* h;     cudaGetSymbolAddress((void**)&h,     g_h);
    int* cnt;     cudaGetSymbolAddress((void**)&cnt,   g_cnt);
    int* rowptr;  cudaGetSymbolAddress((void**)&rowptr,g_rowptr);
    int* cursor;  cudaGetSymbolAddress((void**)&cursor,g_cursor);
    int* csrsrc;  cudaGetSymbolAddress((void**)&csrsrc,g_csrsrc);
    int* blksum;  cudaGetSymbolAddress((void**)&blksum,g_blksum);
    float* dinv;  cudaGetSymbolAddress((void**)&dinv,  g_dinv);

    cudaMemsetAsync(cnt, 0, (size_t)n * sizeof(int));

    // K1: counts
    count_kernel<<<(E + 255) / 256, 256>>>(colArr, cnt, E);

    // K2/K3: scan (+dinv, +cursor init)
    const int nb = (n + SCAN_B - 1) / SCAN_B;
    scanA_kernel<<<nb, SCAN_B>>>(cnt, rowptr, blksum, dinv, n);
    scanB_kernel<<<nb, SCAN_B>>>(rowptr, cursor, blksum, n, E);

    // K4: fused GEMM || fill
    {
        const int nGemm = (n + 63) / 64;
        const int nFill = (E + 255) / 256;
        fused_gemm_fill_kernel<<<nGemm + nFill, 256>>>(
            x, W, dinv, h, rowArr, colArr, cursor, csrsrc, n, E, nGemm);
    }

    // K5: aggregate + epilogue
    {
        const long long threads = (long long)n * 16;
        aggregate_kernel<<<(int)((threads + 255) / 256), 256>>>(
            rowptr, csrsrc, h, dinv, b, out, n);
    }
}

// round 6
// speedup vs baseline: 1.9334x; 1.0734x over previous
#include <cuda_runtime.h>
#include <cuda_fp16.h>
#include <stdint.h>

#define MAXN 100000
#define MAXE 1000000
#define DIN  64
#define DOUT 64
#define SCAN_B 1024

// Scratch (device globals — no allocation allowed)
__device__ __half g_h16[MAXN * DOUT];    // h' = dinv[row] * (x @ W), fp16
__device__ int   g_cnt[MAXN];            // in-degree counts
__device__ int   g_rowptr[MAXN + 1];     // CSR row pointers (by target)
__device__ int   g_cursor[MAXN];         // fill cursors (init = rowptr)
__device__ int   g_csrsrc[MAXE];         // CSR source indices
__device__ int   g_blksum[128];          // scan partials (nb <= 98)
__device__ float g_dinv[MAXN];           // rsqrt(deg + 1)

// ---------------------------------------------------------------------------
// K1: in-degree count over target (col) index
// ---------------------------------------------------------------------------
__global__ void count_kernel(const int* __restrict__ col, int* __restrict__ cnt, int E)
{
    int i = blockIdx.x * blockDim.x + threadIdx.x;
    if (i < E) atomicAdd(&cnt[col[i]], 1);
}

// ---------------------------------------------------------------------------
// K2: scanA — per-block exclusive scan of cnt, block totals, and dinv.
// ---------------------------------------------------------------------------
__global__ void __launch_bounds__(SCAN_B) scanA_kernel(
    const int* __restrict__ cnt, int* __restrict__ rowptr,
    int* __restrict__ blksum, float* __restrict__ dinv, int n)
{
    __shared__ int sh[SCAN_B];
    const int t = threadIdx.x;
    const int i = blockIdx.x * SCAN_B + t;
    const int v = (i < n) ? cnt[i] : 0;
    if (i < n) dinv[i] = rsqrtf((float)v + 1.0f);
    sh[t] = v;
    __syncthreads();
    #pragma unroll
    for (int off = 1; off < SCAN_B; off <<= 1) {
        int add = (t >= off) ? sh[t - off] : 0;
        __syncthreads();
        sh[t] += add;
        __syncthreads();
    }
    if (i < n) rowptr[i] = sh[t] - v;           // exclusive (within block)
    if (t == SCAN_B - 1) blksum[blockIdx.x] = sh[t];
}

// ---------------------------------------------------------------------------
// K3: scanB — finalize rowptr with block prefixes; cursor = rowptr.
// ---------------------------------------------------------------------------
__global__ void __launch_bounds__(SCAN_B) scanB_kernel(
    int* __restrict__ rowptr, int* __restrict__ cursor,
    const int* __restrict__ blksum, int n, int E)
{
    __shared__ int red[128];
    const int t = threadIdx.x;
    if (t < 128) {
        int s = 0;
        for (int j = t; j < blockIdx.x; j += 128) s += blksum[j];
        red[t] = s;
    }
    __syncthreads();
    #pragma unroll
    for (int off = 64; off >= 1; off >>= 1) {
        if (t < off) red[t] += red[t + off];
        __syncthreads();
    }
    const int p = red[0];

    const int i = blockIdx.x * SCAN_B + t;
    if (i < n) {
        const int r = rowptr[i] + p;
        rowptr[i] = r;
        cursor[i] = r;
    }
    if (blockIdx.x == 0 && t == 0) rowptr[n] = E;
}

// ---------------------------------------------------------------------------
// K4: fused GEMM (h16 = fp16(dinv * xW)) || CSR fill.
// GEMM: 256 threads, 8 rows x 8 cols per thread -> 256 rows x 64 cols/block.
// k split into 2 chunks of 32 (xst 32KB + Ws 16KB = 48KB smem).
// ---------------------------------------------------------------------------
__global__ void __launch_bounds__(256) fused_gemm_fill_kernel(
    const float* __restrict__ x, const float* __restrict__ W,
    const float* __restrict__ dinv, __half* __restrict__ h16,
    const int* __restrict__ rowArr, const int* __restrict__ colArr,
    int* __restrict__ cursor, int* __restrict__ csrsrc,
    int n, int E, int nGemm)
{
    __shared__ float Ws[DIN * DOUT];      // 16 KB
    __shared__ float xst[32][256];        // 32 KB (transposed chunk)

    const int tid = threadIdx.x;

    if (blockIdx.x >= nGemm) {
        // ---- fill branch ----
        const int i = (blockIdx.x - nGemm) * 256 + tid;
        if (i < E) {
            const int c = colArr[i];
            const int slot = atomicAdd(&cursor[c], 1);
            csrsrc[slot] = rowArr[i];
        }
        return;
    }

    // ---- GEMM branch ----
    const int tx = tid & 7;               // col octet: cols tx*8..tx*8+7
    const int ty = tid >> 3;              // 0..31  : rows ty*8..ty*8+7
    const int row0 = blockIdx.x * 256;

    // load full W once
    {
        const float4* W4 = reinterpret_cast<const float4*>(W);
        float4* Ws4 = reinterpret_cast<float4*>(Ws);
        #pragma unroll
        for (int i = tid; i < (DIN * DOUT) / 4; i += 256) Ws4[i] = W4[i];
    }

    float acc[8][8];
    #pragma unroll
    for (int r = 0; r < 8; r++)
        #pragma unroll
        for (int c = 0; c < 8; c++) acc[r][c] = 0.f;

    const int myrow = row0 + tid;         // row this thread stages
    const bool rowok = (myrow < n);

    #pragma unroll
    for (int ch = 0; ch < 2; ch++) {
        __syncthreads();   // protect xst reuse (and W load on first pass)
        // stage x chunk transposed: d in [ch*32, ch*32+32)
        if (rowok) {
            #pragma unroll
            for (int q = 0; q < 8; q++) {
                const float4 v = reinterpret_cast<const float4*>(
                    x + (size_t)myrow * DIN + ch * 32)[q];
                xst[q * 4 + 0][tid] = v.x;
                xst[q * 4 + 1][tid] = v.y;
                xst[q * 4 + 2][tid] = v.z;
                xst[q * 4 + 3][tid] = v.w;
            }
        } else {
            #pragma unroll
            for (int q = 0; q < 8; q++) {
                xst[q * 4 + 0][tid] = 0.f;
                xst[q * 4 + 1][tid] = 0.f;
                xst[q * 4 + 2][tid] = 0.f;
                xst[q * 4 + 3][tid] = 0.f;
            }
        }
        __syncthreads();

        #pragma unroll
        for (int d = 0; d < 32; d++) {
            const int gd = ch * 32 + d;
            const float4 xv0 = *reinterpret_cast<const float4*>(&xst[d][ty * 8]);
            const float4 xv1 = *reinterpret_cast<const float4*>(&xst[d][ty * 8 + 4]);
            const float4 wv0 = *reinterpret_cast<const float4*>(&Ws[gd * DOUT + tx * 8]);
            const float4 wv1 = *reinterpret_cast<const float4*>(&Ws[gd * DOUT + tx * 8 + 4]);
            const float xr[8] = {xv0.x, xv0.y, xv0.z, xv0.w, xv1.x, xv1.y, xv1.z, xv1.w};
            const float wc[8] = {wv0.x, wv0.y, wv0.z, wv0.w, wv1.x, wv1.y, wv1.z, wv1.w};
            #pragma unroll
            for (int r = 0; r < 8; r++)
                #pragma unroll
                for (int c = 0; c < 8; c++)
                    acc[r][c] = fmaf(xr[r], wc[c], acc[r][c]);
        }
    }

    // scaled fp16 store: h16[row] = fp16(dinv[row] * acc)
    // 8 half-columns per thread = 16 bytes = one uint4 store (16B-aligned: tx*8 halves).
    #pragma unroll
    for (int r = 0; r < 8; r++) {
        const int grow = row0 + ty * 8 + r;
        if (grow < n) {
            const float s = __ldg(&dinv[grow]);
            __half2 hh[4];
            #pragma unroll
            for (int q = 0; q < 4; q++)
                hh[q] = __floats2half2_rn(s * acc[r][2 * q], s * acc[r][2 * q + 1]);
            *reinterpret_cast<uint4*>(h16 + (size_t)grow * DOUT + tx * 8) =
                *reinterpret_cast<uint4*>(hh);
        }
    }
}

// ---------------------------------------------------------------------------
// K5: aggregate + epilogue. 8 lanes per target node, 8 halves (16B) per lane.
//     out[i] = relu(dinv[i] * (h'[i] + sum_{j in CSR[i]} h'[j]) + b)
// ---------------------------------------------------------------------------
__global__ void __launch_bounds__(256) aggregate_kernel(
    const int* __restrict__ rowptr, const int* __restrict__ csrsrc,
    const __half* __restrict__ h16, const float* __restrict__ dinv,
    const float* __restrict__ b, float* __restrict__ out, int n)
{
    const int gid  = blockIdx.x * blockDim.x + threadIdx.x;
    const int node = gid >> 3;
    const int lane = gid & 7;
    if (node >= n) return;

    const int beg = __ldg(&rowptr[node]);
    const int end = __ldg(&rowptr[node + 1]);

    float acc[8];
    // self loop
    {
        const uint4 hv = reinterpret_cast<const uint4*>(h16 + (size_t)node * DOUT)[lane];
        const __half2* hp = reinterpret_cast<const __half2*>(&hv);
        #pragma unroll
        for (int q = 0; q < 4; q++) {
            const float2 f = __half22float2(hp[q]);
            acc[2 * q]     = f.x;
            acc[2 * q + 1] = f.y;
        }
    }

    int k = beg;
    for (; k + 3 < end; k += 4) {
        const int s0 = __ldg(&csrsrc[k + 0]);
        const int s1 = __ldg(&csrsrc[k + 1]);
        const int s2 = __ldg(&csrsrc[k + 2]);
        const int s3 = __ldg(&csrsrc[k + 3]);
        const uint4 a0 = reinterpret_cast<const uint4*>(h16 + (size_t)s0 * DOUT)[lane];
        const uint4 a1 = reinterpret_cast<const uint4*>(h16 + (size_t)s1 * DOUT)[lane];
        const uint4 a2 = reinterpret_cast<const uint4*>(h16 + (size_t)s2 * DOUT)[lane];
        const uint4 a3 = reinterpret_cast<const uint4*>(h16 + (size_t)s3 * DOUT)[lane];
        const __half2* p0 = reinterpret_cast<const __half2*>(&a0);
        const __half2* p1 = reinterpret_cast<const __half2*>(&a1);
        const __half2* p2 = reinterpret_cast<const __half2*>(&a2);
        const __half2* p3 = reinterpret_cast<const __half2*>(&a3);
        #pragma unroll
        for (int q = 0; q < 4; q++) {
            const float2 f0 = __half22float2(p0[q]);
            const float2 f1 = __half22float2(p1[q]);
            const float2 f2 = __half22float2(p2[q]);
            const float2 f3 = __half22float2(p3[q]);
            acc[2 * q]     += (f0.x + f1.x) + (f2.x + f3.x);
            acc[2 * q + 1] += (f0.y + f1.y) + (f2.y + f3.y);
        }
    }
    for (; k < end; k++) {
        const int s = __ldg(&csrsrc[k]);
        const uint4 a = reinterpret_cast<const uint4*>(h16 + (size_t)s * DOUT)[lane];
        const __half2* p = reinterpret_cast<const __half2*>(&a);
        #pragma unroll
        for (int q = 0; q < 4; q++) {
            const float2 f = __half22float2(p[q]);
            acc[2 * q]     += f.x;
            acc[2 * q + 1] += f.y;
        }
    }

    const float sc = __ldg(&dinv[node]);
    const float4 bb0 = reinterpret_cast<const float4*>(b)[lane * 2];
    const float4 bb1 = reinterpret_cast<const float4*>(b)[lane * 2 + 1];
    float4 o0, o1;
    o0.x = fmaxf(fmaf(sc, acc[0], bb0.x), 0.f);
    o0.y = fmaxf(fmaf(sc, acc[1], bb0.y), 0.f);
    o0.z = fmaxf(fmaf(sc, acc[2], bb0.z), 0.f);
    o0.w = fmaxf(fmaf(sc, acc[3], bb0.w), 0.f);
    o1.x = fmaxf(fmaf(sc, acc[4], bb1.x), 0.f);
    o1.y = fmaxf(fmaf(sc, acc[5], bb1.y), 0.f);
    o1.z = fmaxf(fmaf(sc, acc[6], bb1.z), 0.f);
    o1.w = fmaxf(fmaf(sc, acc[7], bb1.w), 0.f);
    float4* dst = reinterpret_cast<float4*>(out + (size_t)node * DOUT + lane * 8);
    dst[0] = o0;
    dst[1] = o1;
}

// ---------------------------------------------------------------------------
// kernel_launch
// inputs: x [N*64] f32, edge_index [2*E] i32, W [64*64] f32, b [64] f32
// ---------------------------------------------------------------------------
extern "C" void kernel_launch(void* const* d_in, const int* in_sizes, int n_in,
                              void* d_out, int out_size)
{
    const float* x  = (const float*)d_in[0];
    const int*   ei = (const int*)  d_in[1];
    const float* W  = (const float*)d_in[2];
    const float* b  = (const float*)d_in[3];
    float* out      = (float*)d_out;

    const int n = in_sizes[0] / DIN;       // 100000
    const int E = in_sizes[1] / 2;         // 1000000
    const int* rowArr = ei;
    const int* colArr = ei + E;

    __half* h16;  cudaGetSymbolAddress((void**)&h16,   g_h16);
    int* cnt;     cudaGetSymbolAddress((void**)&cnt,   g_cnt);
    int* rowptr;  cudaGetSymbolAddress((void**)&rowptr,g_rowptr);
    int* cursor;  cudaGetSymbolAddress((void**)&cursor,g_cursor);
    int* csrsrc;  cudaGetSymbolAddress((void**)&csrsrc,g_csrsrc);
    int* blksum;  cudaGetSymbolAddress((void**)&blksum,g_blksum);
    float* dinv;  cudaGetSymbolAddress((void**)&dinv,  g_dinv);

    cudaMemsetAsync(cnt, 0, (size_t)n * sizeof(int));

    // K1: counts
    count_kernel<<<(E + 255) / 256, 256>>>(colArr, cnt, E);

    // K2/K3: scan (+dinv, +cursor init)
    const int nb = (n + SCAN_B - 1) / SCAN_B;
    scanA_kernel<<<nb, SCAN_B>>>(cnt, rowptr, blksum, dinv, n);
    scanB_kernel<<<nb, SCAN_B>>>(rowptr, cursor, blksum, n, E);

    // K4: fused GEMM || fill
    {
        const int nGemm = (n + 255) / 256;
        const int nFill = (E + 255) / 256;
        fused_gemm_fill_kernel<<<nGemm + nFill, 256>>>(
            x, W, dinv, h16, rowArr, colArr, cursor, csrsrc, n, E, nGemm);
    }

    // K5: aggregate + epilogue (8 lanes per node)
    {
        const long long threads = (long long)n * 8;
        aggregate_kernel<<<(int)((threads + 255) / 256), 256>>>(
            rowptr, csrsrc, h16, dinv, b, out, n);
    }
}

// round 7
// speedup vs baseline: 1.9527x; 1.0100x over previous
#include <cuda_runtime.h>
#include <cuda_fp16.h>
#include <stdint.h>

#define MAXN 100000
#define MAXE 1000000
#define DIN  64
#define DOUT 64
#define SCAN_B 1024

typedef unsigned long long ull;

// Scratch (device globals — no allocation allowed)
__device__ __half g_h16[MAXN * DOUT];    // h' = dinv[row] * (x @ W), fp16
__device__ int   g_cnt[MAXN];            // in-degree counts
__device__ int   g_rowptr[MAXN + 1];     // CSR row pointers (by target)
__device__ int   g_cursor[MAXN];         // fill cursors (init = rowptr)
__device__ int   g_csrsrc[MAXE];         // CSR source indices
__device__ int   g_blksum[128];          // scan partials (nb <= 98)
__device__ float g_dinv[MAXN];           // rsqrt(deg + 1)

// ---- packed f32x2 helpers -------------------------------------------------
__device__ __forceinline__ ull pack2(float lo, float hi) {
    ull r;
    asm("mov.b64 %0, {%1, %2};" : "=l"(r) : "f"(lo), "f"(hi));
    return r;
}
__device__ __forceinline__ void unpack2(ull v, float& lo, float& hi) {
    asm("mov.b64 {%0, %1}, %2;" : "=f"(lo), "=f"(hi) : "l"(v));
}
__device__ __forceinline__ void fma2(ull& d, ull a, ull b) {
    asm("fma.rn.f32x2 %0, %1, %2, %0;" : "+l"(d) : "l"(a), "l"(b));
}

// ---------------------------------------------------------------------------
// K1: in-degree count over target (col) index
// ---------------------------------------------------------------------------
__global__ void count_kernel(const int* __restrict__ col, int* __restrict__ cnt, int E)
{
    int i = blockIdx.x * blockDim.x + threadIdx.x;
    if (i < E) atomicAdd(&cnt[col[i]], 1);
}

// ---------------------------------------------------------------------------
// K2: scanA — per-block exclusive scan of cnt, block totals, and dinv.
// ---------------------------------------------------------------------------
__global__ void __launch_bounds__(SCAN_B) scanA_kernel(
    const int* __restrict__ cnt, int* __restrict__ rowptr,
    int* __restrict__ blksum, float* __restrict__ dinv, int n)
{
    __shared__ int sh[SCAN_B];
    const int t = threadIdx.x;
    const int i = blockIdx.x * SCAN_B + t;
    const int v = (i < n) ? cnt[i] : 0;
    if (i < n) dinv[i] = rsqrtf((float)v + 1.0f);
    sh[t] = v;
    __syncthreads();
    #pragma unroll
    for (int off = 1; off < SCAN_B; off <<= 1) {
        int add = (t >= off) ? sh[t - off] : 0;
        __syncthreads();
        sh[t] += add;
        __syncthreads();
    }
    if (i < n) rowptr[i] = sh[t] - v;           // exclusive (within block)
    if (t == SCAN_B - 1) blksum[blockIdx.x] = sh[t];
}

// ---------------------------------------------------------------------------
// K3: scanB — finalize rowptr with block prefixes; cursor = rowptr.
// ---------------------------------------------------------------------------
__global__ void __launch_bounds__(SCAN_B) scanB_kernel(
    int* __restrict__ rowptr, int* __restrict__ cursor,
    const int* __restrict__ blksum, int n, int E)
{
    __shared__ int red[128];
    const int t = threadIdx.x;
    if (t < 128) {
        int s = 0;
        for (int j = t; j < blockIdx.x; j += 128) s += blksum[j];
        red[t] = s;
    }
    __syncthreads();
    #pragma unroll
    for (int off = 64; off >= 1; off >>= 1) {
        if (t < off) red[t] += red[t + off];
        __syncthreads();
    }
    const int p = red[0];

    const int i = blockIdx.x * SCAN_B + t;
    if (i < n) {
        const int r = rowptr[i] + p;
        rowptr[i] = r;
        cursor[i] = r;
    }
    if (blockIdx.x == 0 && t == 0) rowptr[n] = E;
}

// ---------------------------------------------------------------------------
// K4: fused GEMM (h16 = fp16(dinv * xW)) || CSR fill.
// GEMM: 256 threads, 8 rows x 8 cols per thread via fma.rn.f32x2 (FFMA2).
// Fill: 2 edges per thread.
// ---------------------------------------------------------------------------
__global__ void __launch_bounds__(256) fused_gemm_fill_kernel(
    const float* __restrict__ x, const float* __restrict__ W,
    const float* __restrict__ dinv, __half* __restrict__ h16,
    const int* __restrict__ rowArr, const int* __restrict__ colArr,
    int* __restrict__ cursor, int* __restrict__ csrsrc,
    int n, int E, int nGemm)
{
    __shared__ float Ws[DIN * DOUT];      // 16 KB
    __shared__ float xst[32][256];        // 32 KB (transposed chunk)

    const int tid = threadIdx.x;

    if (blockIdx.x >= nGemm) {
        // ---- fill branch: 2 edges per thread ----
        const int base = (blockIdx.x - nGemm) * 512 + tid;
        #pragma unroll
        for (int u = 0; u < 2; u++) {
            const int i = base + u * 256;
            if (i < E) {
                const int c = colArr[i];
                const int slot = atomicAdd(&cursor[c], 1);
                csrsrc[slot] = rowArr[i];
            }
        }
        return;
    }

    // ---- GEMM branch ----
    const int tx = tid & 7;               // col octet: cols tx*8..tx*8+7
    const int ty = tid >> 3;              // 0..31  : rows ty*8..ty*8+7
    const int row0 = blockIdx.x * 256;

    // load full W once
    {
        const float4* W4 = reinterpret_cast<const float4*>(W);
        float4* Ws4 = reinterpret_cast<float4*>(Ws);
        #pragma unroll
        for (int i = tid; i < (DIN * DOUT) / 4; i += 256) Ws4[i] = W4[i];
    }

    // acc2[r][cp] packs output cols (2cp, 2cp+1) for row r
    ull acc2[8][4];
    #pragma unroll
    for (int r = 0; r < 8; r++)
        #pragma unroll
        for (int cp = 0; cp < 4; cp++) acc2[r][cp] = 0ull;

    const int myrow = row0 + tid;         // row this thread stages
    const bool rowok = (myrow < n);

    #pragma unroll
    for (int ch = 0; ch < 2; ch++) {
        __syncthreads();   // protect xst reuse (and W load on first pass)
        // stage x chunk transposed: d in [ch*32, ch*32+32)
        if (rowok) {
            #pragma unroll
            for (int q = 0; q < 8; q++) {
                const float4 v = reinterpret_cast<const float4*>(
                    x + (size_t)myrow * DIN + ch * 32)[q];
                xst[q * 4 + 0][tid] = v.x;
                xst[q * 4 + 1][tid] = v.y;
                xst[q * 4 + 2][tid] = v.z;
                xst[q * 4 + 3][tid] = v.w;
            }
        } else {
            #pragma unroll
            for (int q = 0; q < 8; q++) {
                xst[q * 4 + 0][tid] = 0.f;
                xst[q * 4 + 1][tid] = 0.f;
                xst[q * 4 + 2][tid] = 0.f;
                xst[q * 4 + 3][tid] = 0.f;
            }
        }
        __syncthreads();

        #pragma unroll
        for (int d = 0; d < 32; d++) {
            const int gd = ch * 32 + d;
            // x values for 8 rows (broadcast-duplicated into f32x2 lanes)
            const float4 xv0 = *reinterpret_cast<const float4*>(&xst[d][ty * 8]);
            const float4 xv1 = *reinterpret_cast<const float4*>(&xst[d][ty * 8 + 4]);
            ull xp[8];
            xp[0] = pack2(xv0.x, xv0.x); xp[1] = pack2(xv0.y, xv0.y);
            xp[2] = pack2(xv0.z, xv0.z); xp[3] = pack2(xv0.w, xv0.w);
            xp[4] = pack2(xv1.x, xv1.x); xp[5] = pack2(xv1.y, xv1.y);
            xp[6] = pack2(xv1.z, xv1.z); xp[7] = pack2(xv1.w, xv1.w);
            // W col-pairs straight from smem as 64-bit words
            const ulonglong2 w01 = *reinterpret_cast<const ulonglong2*>(&Ws[gd * DOUT + tx * 8]);
            const ulonglong2 w23 = *reinterpret_cast<const ulonglong2*>(&Ws[gd * DOUT + tx * 8 + 4]);
            const ull wc[4] = {w01.x, w01.y, w23.x, w23.y};
            #pragma unroll
            for (int r = 0; r < 8; r++) {
                fma2(acc2[r][0], xp[r], wc[0]);
                fma2(acc2[r][1], xp[r], wc[1]);
                fma2(acc2[r][2], xp[r], wc[2]);
                fma2(acc2[r][3], xp[r], wc[3]);
            }
        }
    }

    // scaled fp16 store: h16[row] = fp16(dinv[row] * acc), 16B per row-slice
    #pragma unroll
    for (int r = 0; r < 8; r++) {
        const int grow = row0 + ty * 8 + r;
        if (grow < n) {
            const float s = __ldg(&dinv[grow]);
            __half2 hh[4];
            #pragma unroll
            for (int cp = 0; cp < 4; cp++) {
                float lo, hi;
                unpack2(acc2[r][cp], lo, hi);
                hh[cp] = __floats2half2_rn(s * lo, s * hi);
            }
            *reinterpret_cast<uint4*>(h16 + (size_t)grow * DOUT + tx * 8) =
                *reinterpret_cast<uint4*>(hh);
        }
    }
}

// ---------------------------------------------------------------------------
// K5: aggregate + epilogue. 8 lanes per target node, 8 halves (16B) per lane.
//     out[i] = relu(dinv[i] * (h'[i] + sum_{j in CSR[i]} h'[j]) + b)
// ---------------------------------------------------------------------------
__global__ void __launch_bounds__(256) aggregate_kernel(
    const int* __restrict__ rowptr, const int* __restrict__ csrsrc,
    const __half* __restrict__ h16, const float* __restrict__ dinv,
    const float* __restrict__ b, float* __restrict__ out, int n)
{
    const int gid  = blockIdx.x * blockDim.x + threadIdx.x;
    const int node = gid >> 3;
    const int lane = gid & 7;
    if (node >= n) return;

    const int beg = __ldg(&rowptr[node]);
    const int end = __ldg(&rowptr[node + 1]);

    float acc[8];
    // self loop
    {
        const uint4 hv = reinterpret_cast<const uint4*>(h16 + (size_t)node * DOUT)[lane];
        const __half2* hp = reinterpret_cast<const __half2*>(&hv);
        #pragma unroll
        for (int q = 0; q < 4; q++) {
            const float2 f = __half22float2(hp[q]);
            acc[2 * q]     = f.x;
            acc[2 * q + 1] = f.y;
        }
    }

    int k = beg;
    for (; k + 3 < end; k += 4) {
        const int s0 = __ldg(&csrsrc[k + 0]);
        const int s1 = __ldg(&csrsrc[k + 1]);
        const int s2 = __ldg(&csrsrc[k + 2]);
        const int s3 = __ldg(&csrsrc[k + 3]);
        const uint4 a0 = reinterpret_cast<const uint4*>(h16 + (size_t)s0 * DOUT)[lane];
        const uint4 a1 = reinterpret_cast<const uint4*>(h16 + (size_t)s1 * DOUT)[lane];
        const uint4 a2 = reinterpret_cast<const uint4*>(h16 + (size_t)s2 * DOUT)[lane];
        const uint4 a3 = reinterpret_cast<const uint4*>(h16 + (size_t)s3 * DOUT)[lane];
        const __half2* p0 = reinterpret_cast<const __half2*>(&a0);
        const __half2* p1 = reinterpret_cast<const __half2*>(&a1);
        const __half2* p2 = reinterpret_cast<const __half2*>(&a2);
        const __half2* p3 = reinterpret_cast<const __half2*>(&a3);
        #pragma unroll
        for (int q = 0; q < 4; q++) {
            const float2 f0 = __half22float2(p0[q]);
            const float2 f1 = __half22float2(p1[q]);
            const float2 f2 = __half22float2(p2[q]);
            const float2 f3 = __half22float2(p3[q]);
            acc[2 * q]     += (f0.x + f1.x) + (f2.x + f3.x);
            acc[2 * q + 1] += (f0.y + f1.y) + (f2.y + f3.y);
        }
    }
    for (; k < end; k++) {
        const int s = __ldg(&csrsrc[k]);
        const uint4 a = reinterpret_cast<const uint4*>(h16 + (size_t)s * DOUT)[lane];
        const __half2* p = reinterpret_cast<const __half2*>(&a);
        #pragma unroll
        for (int q = 0; q < 4; q++) {
            const float2 f = __half22float2(p[q]);
            acc[2 * q]     += f.x;
            acc[2 * q + 1] += f.y;
        }
    }

    const float sc = __ldg(&dinv[node]);
    const float4 bb0 = reinterpret_cast<const float4*>(b)[lane * 2];
    const float4 bb1 = reinterpret_cast<const float4*>(b)[lane * 2 + 1];
    float4 o0, o1;
    o0.x = fmaxf(fmaf(sc, acc[0], bb0.x), 0.f);
    o0.y = fmaxf(fmaf(sc, acc[1], bb0.y), 0.f);
    o0.z = fmaxf(fmaf(sc, acc[2], bb0.z), 0.f);
    o0.w = fmaxf(fmaf(sc, acc[3], bb0.w), 0.f);
    o1.x = fmaxf(fmaf(sc, acc[4], bb1.x), 0.f);
    o1.y = fmaxf(fmaf(sc, acc[5], bb1.y), 0.f);
    o1.z = fmaxf(fmaf(sc, acc[6], bb1.z), 0.f);
    o1.w = fmaxf(fmaf(sc, acc[7], bb1.w), 0.f);
    float4* dst = reinterpret_cast<float4*>(out + (size_t)node * DOUT + lane * 8);
    dst[0] = o0;
    dst[1] = o1;
}

// ---------------------------------------------------------------------------
// kernel_launch
// inputs: x [N*64] f32, edge_index [2*E] i32, W [64*64] f32, b [64] f32
// ---------------------------------------------------------------------------
extern "C" void kernel_launch(void* const* d_in, const int* in_sizes, int n_in,
                              void* d_out, int out_size)
{
    const float* x  = (const float*)d_in[0];
    const int*   ei = (const int*)  d_in[1];
    const float* W  = (const float*)d_in[2];
    const float* b  = (const float*)d_in[3];
    float* out      = (float*)d_out;

    const int n = in_sizes[0] / DIN;       // 100000
    const int E = in_sizes[1] / 2;         // 1000000
    const int* rowArr = ei;
    const int* colArr = ei + E;

    __half* h16;  cudaGetSymbolAddress((void**)&h16,   g_h16);
    int* cnt;     cudaGetSymbolAddress((void**)&cnt,   g_cnt);
    int* rowptr;  cudaGetSymbolAddress((void**)&rowptr,g_rowptr);
    int* cursor;  cudaGetSymbolAddress((void**)&cursor,g_cursor);
    int* csrsrc;  cudaGetSymbolAddress((void**)&csrsrc,g_csrsrc);
    int* blksum;  cudaGetSymbolAddress((void**)&blksum,g_blksum);
    float* dinv;  cudaGetSymbolAddress((void**)&dinv,  g_dinv);

    cudaMemsetAsync(cnt, 0, (size_t)n * sizeof(int));

    // K1: counts
    count_kernel<<<(E + 255) / 256, 256>>>(colArr, cnt, E);

    // K2/K3: scan (+dinv, +cursor init)
    const int nb = (n + SCAN_B - 1) / SCAN_B;
    scanA_kernel<<<nb, SCAN_B>>>(cnt, rowptr, blksum, dinv, n);
    scanB_kernel<<<nb, SCAN_B>>>(rowptr, cursor, blksum, n, E);

    // K4: fused GEMM || fill
    {
        const int nGemm = (n + 255) / 256;
        const int nFill = (E + 511) / 512;
        fused_gemm_fill_kernel<<<nGemm + nFill, 256>>>(
            x, W, dinv, h16, rowArr, colArr, cursor, csrsrc, n, E, nGemm);
    }

    // K5: aggregate + epilogue (8 lanes per node)
    {
        const long long threads = (long long)n * 8;
        aggregate_kernel<<<(int)((threads + 255) / 256), 256>>>(
            rowptr, csrsrc, h16, dinv, b, out, n);
    }
}

// round 8
// speedup vs baseline: 2.4340x; 1.2465x over previous
#include <cuda_runtime.h>
#include <cuda_fp16.h>
#include <stdint.h>

#define MAXN 100000
#define MAXE 1000000
#define DIN  64
#define DOUT 64
#define SCAN_B 1024

// Scratch (device globals — no allocation allowed)
__device__ __half g_h16[MAXN * DOUT];    // h' = dinv[row] * (x @ W), fp16
__device__ int   g_cnt[MAXN];            // in-degree counts
__device__ int   g_rowptr[MAXN + 1];     // CSR row pointers (by target)
__device__ int   g_cursor[MAXN];         // fill cursors (init = rowptr)
__device__ int   g_csrsrc[MAXE];         // CSR source indices
__device__ int   g_blksum[128];          // scan partials (nb <= 98)
__device__ float g_dinv[MAXN];           // rsqrt(deg + 1)

// ---- tensor-core helpers ----------------------------------------------------
__device__ __forceinline__ void ldsm_x4(uint32_t& r0, uint32_t& r1,
                                        uint32_t& r2, uint32_t& r3, uint32_t addr) {
    asm volatile("ldmatrix.sync.aligned.m8n8.x4.shared.b16 {%0,%1,%2,%3}, [%4];"
                 : "=r"(r0), "=r"(r1), "=r"(r2), "=r"(r3) : "r"(addr));
}
__device__ __forceinline__ void ldsm_x2t(uint32_t& r0, uint32_t& r1, uint32_t addr) {
    asm volatile("ldmatrix.sync.aligned.m8n8.x2.trans.shared.b16 {%0,%1}, [%2];"
                 : "=r"(r0), "=r"(r1) : "r"(addr));
}
__device__ __forceinline__ void mma16816(float& c0, float& c1, float& c2, float& c3,
                                         const uint32_t a[4], uint32_t b0, uint32_t b1) {
    asm volatile(
        "mma.sync.aligned.m16n8k16.row.col.f32.f16.f16.f32 "
        "{%0,%1,%2,%3}, {%4,%5,%6,%7}, {%8,%9}, {%0,%1,%2,%3};"
        : "+f"(c0), "+f"(c1), "+f"(c2), "+f"(c3)
        : "r"(a[0]), "r"(a[1]), "r"(a[2]), "r"(a[3]), "r"(b0), "r"(b1));
}

// ---------------------------------------------------------------------------
// K1: in-degree count over target (col) index
// ---------------------------------------------------------------------------
__global__ void count_kernel(const int* __restrict__ col, int* __restrict__ cnt, int E)
{
    int i = blockIdx.x * blockDim.x + threadIdx.x;
    if (i < E) atomicAdd(&cnt[col[i]], 1);
}

// ---------------------------------------------------------------------------
// K2: scanA — per-block exclusive scan of cnt, block totals, and dinv.
// ---------------------------------------------------------------------------
__global__ void __launch_bounds__(SCAN_B) scanA_kernel(
    const int* __restrict__ cnt, int* __restrict__ rowptr,
    int* __restrict__ blksum, float* __restrict__ dinv, int n)
{
    __shared__ int sh[SCAN_B];
    const int t = threadIdx.x;
    const int i = blockIdx.x * SCAN_B + t;
    const int v = (i < n) ? cnt[i] : 0;
    if (i < n) dinv[i] = rsqrtf((float)v + 1.0f);
    sh[t] = v;
    __syncthreads();
    #pragma unroll
    for (int off = 1; off < SCAN_B; off <<= 1) {
        int add = (t >= off) ? sh[t - off] : 0;
        __syncthreads();
        sh[t] += add;
        __syncthreads();
    }
    if (i < n) rowptr[i] = sh[t] - v;           // exclusive (within block)
    if (t == SCAN_B - 1) blksum[blockIdx.x] = sh[t];
}

// ---------------------------------------------------------------------------
// K3: scanB — finalize rowptr with block prefixes; cursor = rowptr.
// ---------------------------------------------------------------------------
__global__ void __launch_bounds__(SCAN_B) scanB_kernel(
    int* __restrict__ rowptr, int* __restrict__ cursor,
    const int* __restrict__ blksum, int n, int E)
{
    __shared__ int red[128];
    const int t = threadIdx.x;
    if (t < 128) {
        int s = 0;
        for (int j = t; j < blockIdx.x; j += 128) s += blksum[j];
        red[t] = s;
    }
    __syncthreads();
    #pragma unroll
    for (int off = 64; off >= 1; off >>= 1) {
        if (t < off) red[t] += red[t + off];
        __syncthreads();
    }
    const int p = red[0];

    const int i = blockIdx.x * SCAN_B + t;
    if (i < n) {
        const int r = rowptr[i] + p;
        rowptr[i] = r;
        cursor[i] = r;
    }
    if (blockIdx.x == 0 && t == 0) rowptr[n] = E;
}

// ---------------------------------------------------------------------------
// K4: fused tensor-core GEMM (h16 = fp16(dinv * xW)) || CSR fill.
// GEMM: 256 threads = 8 warps, 128 rows/block. Each warp: 16 rows x 64 cols
// via mma.sync.m16n8k16 (fp16 in, fp32 accum). x and W converted to fp16 in
// smem with 72-half padded rows (conflict-free ldmatrix).
// Fill: 2 edges per thread.
// ---------------------------------------------------------------------------
__global__ void __launch_bounds__(256) fused_gemm_fill_kernel(
    const float* __restrict__ x, const float* __restrict__ W,
    const float* __restrict__ dinv, __half* __restrict__ h16,
    const int* __restrict__ rowArr, const int* __restrict__ colArr,
    int* __restrict__ cursor, int* __restrict__ csrsrc,
    int n, int E, int nGemm)
{
    __shared__ __half Wh[64][72];     // ~9.2 KB
    __shared__ __half xh[128][72];    // ~18.4 KB

    const int tid = threadIdx.x;

    if (blockIdx.x >= nGemm) {
        // ---- fill branch: 2 edges per thread ----
        const int base = (blockIdx.x - nGemm) * 512 + tid;
        #pragma unroll
        for (int u = 0; u < 2; u++) {
            const int i = base + u * 256;
            if (i < E) {
                const int c = colArr[i];
                const int slot = atomicAdd(&cursor[c], 1);
                csrsrc[slot] = rowArr[i];
            }
        }
        return;
    }

    // ---- GEMM branch ----
    const int row0 = blockIdx.x * 128;

    // convert W (64x64 f32 -> fp16 smem)
    {
        const float4* W4 = reinterpret_cast<const float4*>(W);
        #pragma unroll
        for (int i = tid; i < 1024; i += 256) {
            const float4 v = W4[i];
            const int row = i >> 4;
            const int col = (i & 15) * 4;
            *reinterpret_cast<__half2*>(&Wh[row][col])     = __floats2half2_rn(v.x, v.y);
            *reinterpret_cast<__half2*>(&Wh[row][col + 2]) = __floats2half2_rn(v.z, v.w);
        }
    }
    // convert x tile (128 rows)
    {
        const float4* x4 = reinterpret_cast<const float4*>(x);
        #pragma unroll
        for (int i = tid; i < 2048; i += 256) {
            const int lr = i >> 4;
            const int q  = i & 15;
            const int gr = row0 + lr;
            const float4 v = (gr < n) ? x4[(size_t)gr * 16 + q]
                                      : make_float4(0.f, 0.f, 0.f, 0.f);
            *reinterpret_cast<__half2*>(&xh[lr][q * 4])     = __floats2half2_rn(v.x, v.y);
            *reinterpret_cast<__half2*>(&xh[lr][q * 4 + 2]) = __floats2half2_rn(v.z, v.w);
        }
    }
    __syncthreads();

    const int wid  = tid >> 5;
    const int lane = tid & 31;
    const uint32_t xbase = (uint32_t)__cvta_generic_to_shared(&xh[0][0]);
    const uint32_t wbase = (uint32_t)__cvta_generic_to_shared(&Wh[0][0]);

    // A fragments: 16x64 slice for this warp (4 k-steps of 16)
    uint32_t a[4][4];
    {
        const int ar = lane & 15;
        const int ac = (lane >> 4) * 8;
        #pragma unroll
        for (int kk = 0; kk < 4; kk++) {
            const uint32_t addr =
                xbase + (uint32_t)(((wid * 16 + ar) * 72 + kk * 16 + ac) * 2);
            ldsm_x4(a[kk][0], a[kk][1], a[kk][2], a[kk][3], addr);
        }
    }

    const int r  = lane >> 2;
    const int cq = (lane & 3) * 2;
    const int grow0 = row0 + wid * 16 + r;
    const int grow1 = grow0 + 8;
    const float s0 = (grow0 < n) ? __ldg(&dinv[grow0]) : 0.f;
    const float s1 = (grow1 < n) ? __ldg(&dinv[grow1]) : 0.f;
    const int brow = lane & 15;

    #pragma unroll
    for (int n0 = 0; n0 < 8; n0++) {
        float c0 = 0.f, c1 = 0.f, c2 = 0.f, c3 = 0.f;
        #pragma unroll
        for (int kk = 0; kk < 4; kk++) {
            const uint32_t baddr =
                wbase + (uint32_t)(((kk * 16 + brow) * 72 + n0 * 8) * 2);
            uint32_t b0, b1;
            ldsm_x2t(b0, b1, baddr);
            mma16816(c0, c1, c2, c3, a[kk], b0, b1);
        }
        if (grow0 < n)
            *reinterpret_cast<__half2*>(h16 + (size_t)grow0 * DOUT + n0 * 8 + cq) =
                __floats2half2_rn(s0 * c0, s0 * c1);
        if (grow1 < n)
            *reinterpret_cast<__half2*>(h16 + (size_t)grow1 * DOUT + n0 * 8 + cq) =
                __floats2half2_rn(s1 * c2, s1 * c3);
    }
}

// ---------------------------------------------------------------------------
// K5: aggregate + epilogue. 8 lanes per target node, 8 halves (16B) per lane.
//     out[i] = relu(dinv[i] * (h'[i] + sum_{j in CSR[i]} h'[j]) + b)
// ---------------------------------------------------------------------------
__global__ void __launch_bounds__(256) aggregate_kernel(
    const int* __restrict__ rowptr, const int* __restrict__ csrsrc,
    const __half* __restrict__ h16, const float* __restrict__ dinv,
    const float* __restrict__ b, float* __restrict__ out, int n)
{
    const int gid  = blockIdx.x * blockDim.x + threadIdx.x;
    const int node = gid >> 3;
    const int lane = gid & 7;
    if (node >= n) return;

    const int beg = __ldg(&rowptr[node]);
    const int end = __ldg(&rowptr[node + 1]);

    float acc[8];
    // self loop
    {
        const uint4 hv = reinterpret_cast<const uint4*>(h16 + (size_t)node * DOUT)[lane];
        const __half2* hp = reinterpret_cast<const __half2*>(&hv);
        #pragma unroll
        for (int q = 0; q < 4; q++) {
            const float2 f = __half22float2(hp[q]);
            acc[2 * q]     = f.x;
            acc[2 * q + 1] = f.y;
        }
    }

    int k = beg;
    for (; k + 3 < end; k += 4) {
        const int s0 = __ldg(&csrsrc[k + 0]);
        const int s1 = __ldg(&csrsrc[k + 1]);
        const int s2 = __ldg(&csrsrc[k + 2]);
        const int s3 = __ldg(&csrsrc[k + 3]);
        const uint4 a0 = reinterpret_cast<const uint4*>(h16 + (size_t)s0 * DOUT)[lane];
        const uint4 a1 = reinterpret_cast<const uint4*>(h16 + (size_t)s1 * DOUT)[lane];
        const uint4 a2 = reinterpret_cast<const uint4*>(h16 + (size_t)s2 * DOUT)[lane];
        const uint4 a3 = reinterpret_cast<const uint4*>(h16 + (size_t)s3 * DOUT)[lane];
        const __half2* p0 = reinterpret_cast<const __half2*>(&a0);
        const __half2* p1 = reinterpret_cast<const __half2*>(&a1);
        const __half2* p2 = reinterpret_cast<const __half2*>(&a2);
        const __half2* p3 = reinterpret_cast<const __half2*>(&a3);
        #pragma unroll
        for (int q = 0; q < 4; q++) {
            const float2 f0 = __half22float2(p0[q]);
            const float2 f1 = __half22float2(p1[q]);
            const float2 f2 = __half22float2(p2[q]);
            const float2 f3 = __half22float2(p3[q]);
            acc[2 * q]     += (f0.x + f1.x) + (f2.x + f3.x);
            acc[2 * q + 1] += (f0.y + f1.y) + (f2.y + f3.y);
        }
    }
    for (; k < end; k++) {
        const int s = __ldg(&csrsrc[k]);
        const uint4 a = reinterpret_cast<const uint4*>(h16 + (size_t)s * DOUT)[lane];
        const __half2* p = reinterpret_cast<const __half2*>(&a);
        #pragma unroll
        for (int q = 0; q < 4; q++) {
            const float2 f = __half22float2(p[q]);
            acc[2 * q]     += f.x;
            acc[2 * q + 1] += f.y;
        }
    }

    const float sc = __ldg(&dinv[node]);
    const float4 bb0 = reinterpret_cast<const float4*>(b)[lane * 2];
    const float4 bb1 = reinterpret_cast<const float4*>(b)[lane * 2 + 1];
    float4 o0, o1;
    o0.x = fmaxf(fmaf(sc, acc[0], bb0.x), 0.f);
    o0.y = fmaxf(fmaf(sc, acc[1], bb0.y), 0.f);
    o0.z = fmaxf(fmaf(sc, acc[2], bb0.z), 0.f);
    o0.w = fmaxf(fmaf(sc, acc[3], bb0.w), 0.f);
    o1.x = fmaxf(fmaf(sc, acc[4], bb1.x), 0.f);
    o1.y = fmaxf(fmaf(sc, acc[5], bb1.y), 0.f);
    o1.z = fmaxf(fmaf(sc, acc[6], bb1.z), 0.f);
    o1.w = fmaxf(fmaf(sc, acc[7], bb1.w), 0.f);
    float4* dst = reinterpret_cast<float4*>(out + (size_t)node * DOUT + lane * 8);
    dst[0] = o0;
    dst[1] = o1;
}

// ---------------------------------------------------------------------------
// kernel_launch
// inputs: x [N*64] f32, edge_index [2*E] i32, W [64*64] f32, b [64] f32
// ---------------------------------------------------------------------------
extern "C" void kernel_launch(void* const* d_in, const int* in_sizes, int n_in,
                              void* d_out, int out_size)
{
    const float* x  = (const float*)d_in[0];
    const int*   ei = (const int*)  d_in[1];
    const float* W  = (const float*)d_in[2];
    const float* b  = (const float*)d_in[3];
    float* out      = (float*)d_out;

    const int n = in_sizes[0] / DIN;       // 100000
    const int E = in_sizes[1] / 2;         // 1000000
    const int* rowArr = ei;
    const int* colArr = ei + E;

    __half* h16;  cudaGetSymbolAddress((void**)&h16,   g_h16);
    int* cnt;     cudaGetSymbolAddress((void**)&cnt,   g_cnt);
    int* rowptr;  cudaGetSymbolAddress((void**)&rowptr,g_rowptr);
    int* cursor;  cudaGetSymbolAddress((void**)&cursor,g_cursor);
    int* csrsrc;  cudaGetSymbolAddress((void**)&csrsrc,g_csrsrc);
    int* blksum;  cudaGetSymbolAddress((void**)&blksum,g_blksum);
    float* dinv;  cudaGetSymbolAddress((void**)&dinv,  g_dinv);

    cudaMemsetAsync(cnt, 0, (size_t)n * sizeof(int));

    // K1: counts
    count_kernel<<<(E + 255) / 256, 256>>>(colArr, cnt, E);

    // K2/K3: scan (+dinv, +cursor init)
    const int nb = (n + SCAN_B - 1) / SCAN_B;
    scanA_kernel<<<nb, SCAN_B>>>(cnt, rowptr, blksum, dinv, n);
    scanB_kernel<<<nb, SCAN_B>>>(rowptr, cursor, blksum, n, E);

    // K4: fused tensor-core GEMM || fill
    {
        const int nGemm = (n + 127) / 128;
        const int nFill = (E + 511) / 512;
        fused_gemm_fill_kernel<<<nGemm + nFill, 256>>>(
            x, W, dinv, h16, rowArr, colArr, cursor, csrsrc, n, E, nGemm);
    }

    // K5: aggregate + epilogue (8 lanes per node)
    {
        const long long threads = (long long)n * 8;
        aggregate_kernel<<<(int)((threads + 255) / 256), 256>>>(
            rowptr, csrsrc, h16, dinv, b, out, n);
    }
}